// round 7
// baseline (speedup 1.0000x reference)
#include <cuda_runtime.h>
#include <cuda_bf16.h>

#define NN    1500
#define NEDGE 24000
#define EDIM  64
#define LOOPN 10

#define NBLK  148
#define TPB   512
#define NT_NODE 24          // ceil(1500/64)
#define NT_EDGE 375         // 24000/64

// ---------------- device scratch (static, allocation-free) ----------------
__device__ float g_vc[NN * 8];
__device__ float g_goal[8];
__device__ float g_x[NN * EDIM];
__device__ float g_y[NEDGE * EDIM];
__device__ float g_P[NN * EDIM];
__device__ float g_Q[NN * EDIM];
__device__ float g_agg[NN * EDIM];
__device__ float g_A1[EDIM * EDIM], g_B1[EDIM * EDIM];
__device__ float g_A2[EDIM * EDIM], g_B2[EDIM * EDIM];
__device__ float g_Ay[8 * EDIM],   g_By[8 * EDIM];
__device__ int   g_winner[NN * NN];   // 9 MB

// grid barrier state
__device__ unsigned g_count;
__device__ volatile unsigned g_gen;

#define NEG_INF __int_as_float(0xff800000)

__device__ __forceinline__ void atomicMaxFloat(float* addr, float val) {
    if (val >= 0.0f) atomicMax((int*)addr, __float_as_int(val));
    else             atomicMin((unsigned int*)addr, __float_as_uint(val));
}

// ---- packed f32x2 helpers: ONLY named-register operands, never address-taken ----
__device__ __forceinline__ void ffma2(unsigned long long& d, unsigned long long a,
                                      unsigned long long b) {
    asm("fma.rn.f32x2 %0, %1, %2, %0;" : "+l"(d) : "l"(a), "l"(b));
}
__device__ __forceinline__ unsigned long long pack2(float v) {
    unsigned long long r;
    asm("mov.b64 %0, {%1, %1};" : "=l"(r) : "f"(v));
    return r;
}
__device__ __forceinline__ float2 unpack2(unsigned long long v) {
    float2 r;
    asm("mov.b64 {%0, %1}, %2;" : "=f"(r.x), "=f"(r.y) : "l"(v));
    return r;
}
__device__ __forceinline__ unsigned long long packf2(float a, float b) {
    unsigned long long r;
    asm("mov.b64 %0, {%1, %2};" : "=l"(r) : "f"(a), "f"(b));
    return r;
}

// grid-wide barrier (all NBLK blocks resident)
__device__ __forceinline__ void gsync() {
    __syncthreads();
    if (threadIdx.x == 0) {
        unsigned gen = g_gen;
        __threadfence();
        if (atomicAdd(&g_count, 1u) == NBLK - 1) {
            g_count = 0;
            __threadfence();
            g_gen = gen + 1;
        } else {
            while (g_gen == gen) { }
        }
        __threadfence();
    }
    __syncthreads();
}

// ---------------- prep kernels ----------------

__global__ void k_vc(const float* __restrict__ v, const float* __restrict__ labels) {
    int i = blockIdx.x * blockDim.x + threadIdx.x;
    if (i < NN) {
        #pragma unroll
        for (int j = 0; j < 7; j++) g_vc[i * 8 + j] = v[i * 7 + j];
        g_vc[i * 8 + 7] = labels[i];
    }
}

__global__ void k_goal(const float* __restrict__ labels) {
    __shared__ float bv[256];
    __shared__ int   bi[256];
    int t = threadIdx.x;
    float best = -1e30f; int idx = 0;
    for (int i = t; i < NN; i += 256) {
        float l = labels[i];
        if (l > best) { best = l; idx = i; }
    }
    bv[t] = best; bi[t] = idx;
    __syncthreads();
    for (int s = 128; s > 0; s >>= 1) {
        if (t < s) {
            if (bv[t + s] > bv[t] || (bv[t + s] == bv[t] && bi[t + s] < bi[t])) {
                bv[t] = bv[t + s]; bi[t] = bi[t + s];
            }
        }
        __syncthreads();
    }
    if (t < 8) g_goal[t] = g_vc[bi[0] * 8 + t];
}

__global__ void k_wprep(const float* __restrict__ fxW1, const float* __restrict__ fyW1,
                        const float* __restrict__ hyW1) {
    int t = blockIdx.x * blockDim.x + threadIdx.x;
    if (t < 4096) {
        g_A1[t] = fxW1[t] + fxW1[4096 + t];
        g_B1[t] = fxW1[8192 + t] - fxW1[t];
        g_A2[t] = fyW1[t] + fyW1[4096 + t];
        g_B2[t] = fyW1[8192 + t] - fyW1[t];
        if (t < 512) {
            g_Ay[t] = hyW1[t] + hyW1[512 + t];
            g_By[t] = hyW1[1024 + t] - hyW1[t];
        }
    }
}

__global__ void k_init_x(const float* __restrict__ W1, const float* __restrict__ b1,
                         const float* __restrict__ W2, const float* __restrict__ b2) {
    int i = blockIdx.x;
    int c = threadIdx.x;                 // 64 threads
    __shared__ float z[32], h[64];
    if (c < 8) {
        float vcv = g_vc[i * 8 + c];
        float gl  = g_goal[c];
        float d   = vcv - gl;
        z[c] = vcv; z[8 + c] = gl; z[16 + c] = d; z[24 + c] = d * d;
    }
    __syncthreads();
    float acc = b1[c];
    #pragma unroll
    for (int k = 0; k < 32; k++) acc += z[k] * W1[k * 64 + c];
    h[c] = fmaxf(acc, 0.0f);
    __syncthreads();
    float o = b2[c];
    #pragma unroll 16
    for (int k = 0; k < 64; k++) o += h[k] * W2[k * 64 + c];
    g_x[i * 64 + c] = o;
}

__global__ void k_node8() {
    int i = blockIdx.x, c = threadIdx.x;   // 64 threads
    __shared__ float z[8];
    if (c < 8) z[c] = g_vc[i * 8 + c];
    __syncthreads();
    float r = 0.f, s = 0.f;
    #pragma unroll
    for (int k = 0; k < 8; k++) {
        r += z[k] * g_Ay[k * 64 + c];
        s += z[k] * g_By[k * 64 + c];
    }
    g_P[i * 64 + c] = r;
    g_Q[i * 64 + c] = s;
}

// initial y:  h = relu(P[tgt] + Q[src] + b1); y = h@W2 + b2
__global__ void k_edge_y0(const float* __restrict__ b1, const float* __restrict__ W2,
                          const float* __restrict__ b2,
                          const int* __restrict__ src, const int* __restrict__ tgt) {
    __shared__ float Ws[4096];
    __shared__ float hs[64 * 33];
    int tid = threadIdx.x;
    int e0  = blockIdx.x * 32;
    for (int idx = tid; idx < 4096; idx += 256) Ws[idx] = W2[idx];
    int el = tid >> 3, cg = tid & 7, c0 = cg * 8;
    int e = e0 + el;
    int s = src[e], t = tgt[e];
    #pragma unroll
    for (int j = 0; j < 8; j++) {
        float h = g_P[t * 64 + c0 + j] + g_Q[s * 64 + c0 + j] + b1[c0 + j];
        hs[(c0 + j) * 33 + el] = fmaxf(h, 0.f);
    }
    __syncthreads();
    unsigned long long d0 = packf2(b2[c0 + 0], b2[c0 + 1]);
    unsigned long long d1 = packf2(b2[c0 + 2], b2[c0 + 3]);
    unsigned long long d2 = packf2(b2[c0 + 4], b2[c0 + 5]);
    unsigned long long d3 = packf2(b2[c0 + 6], b2[c0 + 7]);
    #pragma unroll 4
    for (int k = 0; k < 64; k++) {
        unsigned long long hv = pack2(hs[k * 33 + el]);
        ulonglong2 wa = *(const ulonglong2*)&Ws[k * 64 + c0];
        ulonglong2 wb = *(const ulonglong2*)&Ws[k * 64 + c0 + 4];
        ffma2(d0, hv, wa.x); ffma2(d1, hv, wa.y);
        ffma2(d2, hv, wb.x); ffma2(d3, hv, wb.y);
    }
    float2 u0 = unpack2(d0), u1 = unpack2(d1), u2 = unpack2(d2), u3 = unpack2(d3);
    *(float4*)&g_y[e * 64 + c0]     = make_float4(u0.x, u0.y, u1.x, u1.y);
    *(float4*)&g_y[e * 64 + c0 + 4] = make_float4(u2.x, u2.y, u3.x, u3.y);
}

// ---------------- fused persistent loop kernel ----------------
#define SM_A1  0
#define SM_B1  (SM_A1 + 4096)
#define SM_A2  (SM_B1 + 4096)
#define SM_B2  (SM_A2 + 4096)
#define SM_WY  (SM_B2 + 4096)
#define SM_W2X (SM_WY + 4096)
#define SM_W2Y (SM_W2X + 4096)
#define SM_BX1 (SM_W2Y + 4096)
#define SM_BX2 (SM_BX1 + 64)
#define SM_BY1 (SM_BX2 + 64)
#define SM_BY2 (SM_BY1 + 64)
#define SM_YS  (SM_BY2 + 64)
#define SM_HS  (SM_YS + 64 * 65)
#define SM_FLOATS (SM_HS + 64 * 65)

__global__ void __launch_bounds__(TPB, 1)
k_loop(const float* __restrict__ fxW1y, const float* __restrict__ fx_b1,
       const float* __restrict__ fx_W2, const float* __restrict__ fx_b2,
       const float* __restrict__ fy_b1, const float* __restrict__ fy_W2,
       const float* __restrict__ fy_b2,
       const int* __restrict__ src, const int* __restrict__ tgt) {
    extern __shared__ float sm[];
    const int tid = threadIdx.x;
    const int bid = blockIdx.x;

    for (int idx = tid; idx < 4096; idx += TPB) {
        sm[SM_A1 + idx]  = g_A1[idx];
        sm[SM_B1 + idx]  = g_B1[idx];
        sm[SM_A2 + idx]  = g_A2[idx];
        sm[SM_B2 + idx]  = g_B2[idx];
        sm[SM_WY + idx]  = fxW1y[idx];
        sm[SM_W2X + idx] = fx_W2[idx];
        sm[SM_W2Y + idx] = fy_W2[idx];
    }
    if (tid < 64) {
        sm[SM_BX1 + tid] = fx_b1[tid];
        sm[SM_BX2 + tid] = fx_b2[tid];
        sm[SM_BY1 + tid] = fy_b1[tid];
        sm[SM_BY2 + tid] = fy_b2[tid];
    }
    __syncthreads();

    float* ys = sm + SM_YS;
    float* hs = sm + SM_HS;
    const int nl = tid >> 3;          // 0..63 (node/edge lane)
    const int c0 = (tid & 7) * 8;     // column group

    for (int it = 0; it < LOOPN; it++) {
        // ---- Phase 1: P = x@A1, Q = x@B1, agg = -inf ----
        for (int tile = bid; tile < NT_NODE; tile += NBLK) {
            int i0 = tile * 64;
            for (int idx = tid; idx < 4096; idx += TPB) {
                int n2 = idx >> 6, k = idx & 63, i = i0 + n2;
                ys[k * 65 + n2] = (i < NN) ? g_x[i * 64 + k] : 0.f;
            }
            __syncthreads();
            unsigned long long p0 = 0, p1 = 0, p2 = 0, p3 = 0;
            unsigned long long q0 = 0, q1 = 0, q2 = 0, q3 = 0;
            #pragma unroll 4
            for (int k = 0; k < 64; k++) {
                unsigned long long xv = pack2(ys[k * 65 + nl]);
                ulonglong2 a0 = *(const ulonglong2*)&sm[SM_A1 + k * 64 + c0];
                ulonglong2 a1 = *(const ulonglong2*)&sm[SM_A1 + k * 64 + c0 + 4];
                ulonglong2 b0 = *(const ulonglong2*)&sm[SM_B1 + k * 64 + c0];
                ulonglong2 b1 = *(const ulonglong2*)&sm[SM_B1 + k * 64 + c0 + 4];
                ffma2(p0, xv, a0.x); ffma2(p1, xv, a0.y);
                ffma2(p2, xv, a1.x); ffma2(p3, xv, a1.y);
                ffma2(q0, xv, b0.x); ffma2(q1, xv, b0.y);
                ffma2(q2, xv, b1.x); ffma2(q3, xv, b1.y);
            }
            int i = i0 + nl;
            if (i < NN) {
                float2 u0 = unpack2(p0), u1 = unpack2(p1), u2 = unpack2(p2), u3 = unpack2(p3);
                *(float4*)&g_P[i * 64 + c0]     = make_float4(u0.x, u0.y, u1.x, u1.y);
                *(float4*)&g_P[i * 64 + c0 + 4] = make_float4(u2.x, u2.y, u3.x, u3.y);
                float2 v0 = unpack2(q0), v1 = unpack2(q1), v2 = unpack2(q2), v3 = unpack2(q3);
                *(float4*)&g_Q[i * 64 + c0]     = make_float4(v0.x, v0.y, v1.x, v1.y);
                *(float4*)&g_Q[i * 64 + c0 + 4] = make_float4(v2.x, v2.y, v3.x, v3.y);
                float4 ni = make_float4(NEG_INF, NEG_INF, NEG_INF, NEG_INF);
                *(float4*)&g_agg[i * 64 + c0]     = ni;
                *(float4*)&g_agg[i * 64 + c0 + 4] = ni;
            }
            __syncthreads();
        }
        gsync();

        // ---- Phase 2: fx edges: msg = mlp(y@Wy + P[src] + Q[tgt]); atomic agg[tgt] ----
        for (int tile = bid; tile < NT_EDGE; tile += NBLK) {
            int e0 = tile * 64;
            for (int idx = tid; idx < 4096; idx += TPB) {
                int el = idx >> 6, k = idx & 63;
                ys[k * 65 + el] = g_y[(e0 + el) * 64 + k];
            }
            __syncthreads();
            int e = e0 + nl;
            int s = src[e], t = tgt[e];
            unsigned long long m0 = 0, m1 = 0, m2 = 0, m3 = 0;
            #pragma unroll 4
            for (int k = 0; k < 64; k++) {
                unsigned long long yv = pack2(ys[k * 65 + nl]);
                ulonglong2 w0 = *(const ulonglong2*)&sm[SM_WY + k * 64 + c0];
                ulonglong2 w1 = *(const ulonglong2*)&sm[SM_WY + k * 64 + c0 + 4];
                ffma2(m0, yv, w0.x); ffma2(m1, yv, w0.y);
                ffma2(m2, yv, w1.x); ffma2(m3, yv, w1.y);
            }
            float4 pA = *(const float4*)&g_P[s * 64 + c0];
            float4 pB = *(const float4*)&g_P[s * 64 + c0 + 4];
            float4 qA = *(const float4*)&g_Q[t * 64 + c0];
            float4 qB = *(const float4*)&g_Q[t * 64 + c0 + 4];
            float2 u0 = unpack2(m0), u1 = unpack2(m1), u2 = unpack2(m2), u3 = unpack2(m3);
            hs[(c0 + 0) * 65 + nl] = fmaxf(u0.x + pA.x + qA.x + sm[SM_BX1 + c0 + 0], 0.f);
            hs[(c0 + 1) * 65 + nl] = fmaxf(u0.y + pA.y + qA.y + sm[SM_BX1 + c0 + 1], 0.f);
            hs[(c0 + 2) * 65 + nl] = fmaxf(u1.x + pA.z + qA.z + sm[SM_BX1 + c0 + 2], 0.f);
            hs[(c0 + 3) * 65 + nl] = fmaxf(u1.y + pA.w + qA.w + sm[SM_BX1 + c0 + 3], 0.f);
            hs[(c0 + 4) * 65 + nl] = fmaxf(u2.x + pB.x + qB.x + sm[SM_BX1 + c0 + 4], 0.f);
            hs[(c0 + 5) * 65 + nl] = fmaxf(u2.y + pB.y + qB.y + sm[SM_BX1 + c0 + 5], 0.f);
            hs[(c0 + 6) * 65 + nl] = fmaxf(u3.x + pB.z + qB.z + sm[SM_BX1 + c0 + 6], 0.f);
            hs[(c0 + 7) * 65 + nl] = fmaxf(u3.y + pB.w + qB.w + sm[SM_BX1 + c0 + 7], 0.f);
            __syncthreads();
            unsigned long long d0 = *(const unsigned long long*)&sm[SM_BX2 + c0];
            unsigned long long d1 = *(const unsigned long long*)&sm[SM_BX2 + c0 + 2];
            unsigned long long d2 = *(const unsigned long long*)&sm[SM_BX2 + c0 + 4];
            unsigned long long d3 = *(const unsigned long long*)&sm[SM_BX2 + c0 + 6];
            #pragma unroll 4
            for (int k = 0; k < 64; k++) {
                unsigned long long hv = pack2(hs[k * 65 + nl]);
                ulonglong2 w0 = *(const ulonglong2*)&sm[SM_W2X + k * 64 + c0];
                ulonglong2 w1 = *(const ulonglong2*)&sm[SM_W2X + k * 64 + c0 + 4];
                ffma2(d0, hv, w0.x); ffma2(d1, hv, w0.y);
                ffma2(d2, hv, w1.x); ffma2(d3, hv, w1.y);
            }
            float2 r0 = unpack2(d0), r1 = unpack2(d1), r2 = unpack2(d2), r3 = unpack2(d3);
            atomicMaxFloat(&g_agg[t * 64 + c0 + 0], r0.x);
            atomicMaxFloat(&g_agg[t * 64 + c0 + 1], r0.y);
            atomicMaxFloat(&g_agg[t * 64 + c0 + 2], r1.x);
            atomicMaxFloat(&g_agg[t * 64 + c0 + 3], r1.y);
            atomicMaxFloat(&g_agg[t * 64 + c0 + 4], r2.x);
            atomicMaxFloat(&g_agg[t * 64 + c0 + 5], r2.y);
            atomicMaxFloat(&g_agg[t * 64 + c0 + 6], r3.x);
            atomicMaxFloat(&g_agg[t * 64 + c0 + 7], r3.y);
            __syncthreads();
        }
        gsync();

        // ---- Phase 3: x = max(x, fix(agg)); P = x@A2, Q = x@B2 ----
        for (int tile = bid; tile < NT_NODE; tile += NBLK) {
            int i0 = tile * 64;
            int i = i0 + nl;
            if (i < NN) {
                float4 a0 = *(const float4*)&g_agg[i * 64 + c0];
                float4 a1 = *(const float4*)&g_agg[i * 64 + c0 + 4];
                float4 x0 = *(const float4*)&g_x[i * 64 + c0];
                float4 x1 = *(const float4*)&g_x[i * 64 + c0 + 4];
                float xn0 = fmaxf(x0.x, (a0.x == NEG_INF) ? 0.f : a0.x);
                float xn1 = fmaxf(x0.y, (a0.y == NEG_INF) ? 0.f : a0.y);
                float xn2 = fmaxf(x0.z, (a0.z == NEG_INF) ? 0.f : a0.z);
                float xn3 = fmaxf(x0.w, (a0.w == NEG_INF) ? 0.f : a0.w);
                float xn4 = fmaxf(x1.x, (a1.x == NEG_INF) ? 0.f : a1.x);
                float xn5 = fmaxf(x1.y, (a1.y == NEG_INF) ? 0.f : a1.y);
                float xn6 = fmaxf(x1.z, (a1.z == NEG_INF) ? 0.f : a1.z);
                float xn7 = fmaxf(x1.w, (a1.w == NEG_INF) ? 0.f : a1.w);
                *(float4*)&g_x[i * 64 + c0]     = make_float4(xn0, xn1, xn2, xn3);
                *(float4*)&g_x[i * 64 + c0 + 4] = make_float4(xn4, xn5, xn6, xn7);
                ys[(c0 + 0) * 65 + nl] = xn0; ys[(c0 + 1) * 65 + nl] = xn1;
                ys[(c0 + 2) * 65 + nl] = xn2; ys[(c0 + 3) * 65 + nl] = xn3;
                ys[(c0 + 4) * 65 + nl] = xn4; ys[(c0 + 5) * 65 + nl] = xn5;
                ys[(c0 + 6) * 65 + nl] = xn6; ys[(c0 + 7) * 65 + nl] = xn7;
            } else {
                #pragma unroll
                for (int j = 0; j < 8; j++) ys[(c0 + j) * 65 + nl] = 0.f;
            }
            __syncthreads();
            unsigned long long p0 = 0, p1 = 0, p2 = 0, p3 = 0;
            unsigned long long q0 = 0, q1 = 0, q2 = 0, q3 = 0;
            #pragma unroll 4
            for (int k = 0; k < 64; k++) {
                unsigned long long xv = pack2(ys[k * 65 + nl]);
                ulonglong2 a0 = *(const ulonglong2*)&sm[SM_A2 + k * 64 + c0];
                ulonglong2 a1 = *(const ulonglong2*)&sm[SM_A2 + k * 64 + c0 + 4];
                ulonglong2 b0 = *(const ulonglong2*)&sm[SM_B2 + k * 64 + c0];
                ulonglong2 b1 = *(const ulonglong2*)&sm[SM_B2 + k * 64 + c0 + 4];
                ffma2(p0, xv, a0.x); ffma2(p1, xv, a0.y);
                ffma2(p2, xv, a1.x); ffma2(p3, xv, a1.y);
                ffma2(q0, xv, b0.x); ffma2(q1, xv, b0.y);
                ffma2(q2, xv, b1.x); ffma2(q3, xv, b1.y);
            }
            if (i < NN) {
                float2 u0 = unpack2(p0), u1 = unpack2(p1), u2 = unpack2(p2), u3 = unpack2(p3);
                *(float4*)&g_P[i * 64 + c0]     = make_float4(u0.x, u0.y, u1.x, u1.y);
                *(float4*)&g_P[i * 64 + c0 + 4] = make_float4(u2.x, u2.y, u3.x, u3.y);
                float2 v0 = unpack2(q0), v1 = unpack2(q1), v2 = unpack2(q2), v3 = unpack2(q3);
                *(float4*)&g_Q[i * 64 + c0]     = make_float4(v0.x, v0.y, v1.x, v1.y);
                *(float4*)&g_Q[i * 64 + c0 + 4] = make_float4(v2.x, v2.y, v3.x, v3.y);
            }
            __syncthreads();
        }
        gsync();

        // ---- Phase 4: fy edges: y = max(y, mlp(P[tgt] + Q[src])) ----
        for (int tile = bid; tile < NT_EDGE; tile += NBLK) {
            int e0 = tile * 64;
            int e = e0 + nl;
            int s = src[e], t = tgt[e];
            float4 pA = *(const float4*)&g_P[t * 64 + c0];
            float4 pB = *(const float4*)&g_P[t * 64 + c0 + 4];
            float4 qA = *(const float4*)&g_Q[s * 64 + c0];
            float4 qB = *(const float4*)&g_Q[s * 64 + c0 + 4];
            hs[(c0 + 0) * 65 + nl] = fmaxf(pA.x + qA.x + sm[SM_BY1 + c0 + 0], 0.f);
            hs[(c0 + 1) * 65 + nl] = fmaxf(pA.y + qA.y + sm[SM_BY1 + c0 + 1], 0.f);
            hs[(c0 + 2) * 65 + nl] = fmaxf(pA.z + qA.z + sm[SM_BY1 + c0 + 2], 0.f);
            hs[(c0 + 3) * 65 + nl] = fmaxf(pA.w + qA.w + sm[SM_BY1 + c0 + 3], 0.f);
            hs[(c0 + 4) * 65 + nl] = fmaxf(pB.x + qB.x + sm[SM_BY1 + c0 + 4], 0.f);
            hs[(c0 + 5) * 65 + nl] = fmaxf(pB.y + qB.y + sm[SM_BY1 + c0 + 5], 0.f);
            hs[(c0 + 6) * 65 + nl] = fmaxf(pB.z + qB.z + sm[SM_BY1 + c0 + 6], 0.f);
            hs[(c0 + 7) * 65 + nl] = fmaxf(pB.w + qB.w + sm[SM_BY1 + c0 + 7], 0.f);
            __syncthreads();
            unsigned long long d0 = *(const unsigned long long*)&sm[SM_BY2 + c0];
            unsigned long long d1 = *(const unsigned long long*)&sm[SM_BY2 + c0 + 2];
            unsigned long long d2 = *(const unsigned long long*)&sm[SM_BY2 + c0 + 4];
            unsigned long long d3 = *(const unsigned long long*)&sm[SM_BY2 + c0 + 6];
            #pragma unroll 4
            for (int k = 0; k < 64; k++) {
                unsigned long long hv = pack2(hs[k * 65 + nl]);
                ulonglong2 w0 = *(const ulonglong2*)&sm[SM_W2Y + k * 64 + c0];
                ulonglong2 w1 = *(const ulonglong2*)&sm[SM_W2Y + k * 64 + c0 + 4];
                ffma2(d0, hv, w0.x); ffma2(d1, hv, w0.y);
                ffma2(d2, hv, w1.x); ffma2(d3, hv, w1.y);
            }
            float4 y0 = *(const float4*)&g_y[e * 64 + c0];
            float4 y1 = *(const float4*)&g_y[e * 64 + c0 + 4];
            float2 r0 = unpack2(d0), r1 = unpack2(d1), r2 = unpack2(d2), r3 = unpack2(d3);
            y0.x = fmaxf(y0.x, r0.x); y0.y = fmaxf(y0.y, r0.y);
            y0.z = fmaxf(y0.z, r1.x); y0.w = fmaxf(y0.w, r1.y);
            y1.x = fmaxf(y1.x, r2.x); y1.y = fmaxf(y1.y, r2.y);
            y1.z = fmaxf(y1.z, r3.x); y1.w = fmaxf(y1.w, r3.y);
            *(float4*)&g_y[e * 64 + c0]     = y0;
            *(float4*)&g_y[e * 64 + c0 + 4] = y1;
            __syncthreads();
        }
        gsync();
    }
}

// ---------------- output kernels ----------------
__global__ void k_winner_init() {
    int i = blockIdx.x * blockDim.x + threadIdx.x;
    if (i < NN * NN) g_winner[i] = -1;
}

__global__ void k_winner(const int* __restrict__ src, const int* __restrict__ tgt) {
    int e = blockIdx.x * blockDim.x + threadIdx.x;
    if (e < NEDGE) atomicMax(&g_winner[src[e] * NN + tgt[e]], e);
}

__global__ void k_scatter(const int* __restrict__ src, const int* __restrict__ tgt,
                          float* __restrict__ out) {
    int idx = blockIdx.x * blockDim.x + threadIdx.x;
    if (idx < NEDGE * EDIM) {
        int e = idx >> 6, c = idx & 63;
        int s = src[e], t = tgt[e];
        long long slot = (long long)s * NN + t;
        if (g_winner[slot] == e) out[slot * 64 + c] = g_y[idx];
    }
}

__global__ void k_out_x(float* __restrict__ out) {
    int i = blockIdx.x * blockDim.x + threadIdx.x;
    if (i < NN * EDIM) out[(long long)NN * NN * EDIM + i] = g_x[i];
}

// ---------------- launch ----------------
extern "C" void kernel_launch(void* const* d_in, const int* in_sizes, int n_in,
                              void* d_out, int out_size) {
    const float* v      = (const float*)d_in[0];
    const float* labels = (const float*)d_in[1];
    const int*   ei     = (const int*)d_in[4];
    const float* hx_W1 = (const float*)d_in[6],  *hx_b1 = (const float*)d_in[7];
    const float* hx_W2 = (const float*)d_in[8],  *hx_b2 = (const float*)d_in[9];
    const float* hy_W1 = (const float*)d_in[10], *hy_b1 = (const float*)d_in[11];
    const float* hy_W2 = (const float*)d_in[12], *hy_b2 = (const float*)d_in[13];
    const float* fx_W1 = (const float*)d_in[14], *fx_b1 = (const float*)d_in[15];
    const float* fx_W2 = (const float*)d_in[16], *fx_b2 = (const float*)d_in[17];
    const float* fy_W1 = (const float*)d_in[18], *fy_b1 = (const float*)d_in[19];
    const float* fy_W2 = (const float*)d_in[20], *fy_b2 = (const float*)d_in[21];

    const int* src = ei;
    const int* tgt = ei + NEDGE;
    float* out = (float*)d_out;

    cudaFuncSetAttribute(k_loop, cudaFuncAttributeMaxDynamicSharedMemorySize,
                         SM_FLOATS * sizeof(float));

    // side stream: big memset + winner machinery overlaps the loop
    cudaStream_t s2;
    cudaStreamCreateWithFlags(&s2, cudaStreamNonBlocking);
    cudaEvent_t evFork, evJoin;
    cudaEventCreateWithFlags(&evFork, cudaEventDisableTiming);
    cudaEventCreateWithFlags(&evJoin, cudaEventDisableTiming);

    cudaEventRecord(evFork, 0);
    cudaStreamWaitEvent(s2, evFork, 0);
    cudaMemsetAsync(d_out, 0, (size_t)NN * NN * EDIM * sizeof(float), s2);
    k_winner_init<<<(NN * NN + 255) / 256, 256, 0, s2>>>();
    k_winner<<<(NEDGE + 255) / 256, 256, 0, s2>>>(src, tgt);
    cudaEventRecord(evJoin, s2);

    // main stream: prelude
    k_vc<<<(NN + 255) / 256, 256>>>(v, labels);
    k_goal<<<1, 256>>>(labels);
    k_wprep<<<16, 256>>>(fx_W1, fy_W1, hy_W1);
    k_init_x<<<NN, 64>>>(hx_W1, hx_b1, hx_W2, hx_b2);
    k_node8<<<NN, 64>>>();
    k_edge_y0<<<NEDGE / 32, 256>>>(hy_b1, hy_W2, hy_b2, src, tgt);

    // fused 10-iteration loop (persistent, grid barriers inside)
    k_loop<<<NBLK, TPB, SM_FLOATS * sizeof(float)>>>(
        fx_W1 + 192 * 64, fx_b1, fx_W2, fx_b2, fy_b1, fy_W2, fy_b2, src, tgt);

    // join side stream, then output
    cudaStreamWaitEvent(0, evJoin, 0);
    k_scatter<<<(NEDGE * EDIM + 255) / 256, 256>>>(src, tgt, out);
    k_out_x<<<(NN * EDIM + 255) / 256, 256>>>(out);
}

// round 8
// speedup vs baseline: 1.1005x; 1.1005x over previous
#include <cuda_runtime.h>
#include <cuda_bf16.h>

#define NN    1500
#define NEDGE 24000
#define EDIM  64
#define LOOPN 10

// ---------------- device scratch (static, allocation-free) ----------------
__device__ float g_vc[NN * 8];
__device__ float g_goal[8];
__device__ float g_x[NN * EDIM];
__device__ float g_y[NEDGE * EDIM];
__device__ float g_P[NN * EDIM];
__device__ float g_Q[NN * EDIM];
__device__ float g_agg[NN * EDIM];
__device__ float g_A1[EDIM * EDIM], g_B1[EDIM * EDIM];
__device__ float g_A2[EDIM * EDIM], g_B2[EDIM * EDIM];
__device__ float g_Ay[8 * EDIM],   g_By[8 * EDIM];
__device__ int   g_winner[NN * NN];   // 9 MB

#define NEG_INF __int_as_float(0xff800000)

__device__ __forceinline__ void atomicMaxFloat(float* addr, float val) {
    if (val >= 0.0f) atomicMax((int*)addr, __float_as_int(val));
    else             atomicMin((unsigned int*)addr, __float_as_uint(val));
}

#define FMA8(acc, v, w0, w1)                                   \
    {   acc[0] += (v) * (w0).x; acc[1] += (v) * (w0).y;        \
        acc[2] += (v) * (w0).z; acc[3] += (v) * (w0).w;        \
        acc[4] += (v) * (w1).x; acc[5] += (v) * (w1).y;        \
        acc[6] += (v) * (w1).z; acc[7] += (v) * (w1).w; }

// ---------------- prep kernels ----------------

// fused: build vc, then find goal row (single block)
__global__ void k_prep0(const float* __restrict__ v, const float* __restrict__ labels) {
    __shared__ float bv[256];
    __shared__ int   bi[256];
    int t = threadIdx.x;
    for (int i = t; i < NN; i += 256) {
        #pragma unroll
        for (int j = 0; j < 7; j++) g_vc[i * 8 + j] = v[i * 7 + j];
        g_vc[i * 8 + 7] = labels[i];
    }
    float best = -1e30f; int idx = 0;
    for (int i = t; i < NN; i += 256) {
        float l = labels[i];
        if (l > best) { best = l; idx = i; }
    }
    bv[t] = best; bi[t] = idx;
    __syncthreads();
    for (int s = 128; s > 0; s >>= 1) {
        if (t < s) {
            if (bv[t + s] > bv[t] || (bv[t + s] == bv[t] && bi[t + s] < bi[t])) {
                bv[t] = bv[t + s]; bi[t] = bi[t + s];
            }
        }
        __syncthreads();
    }
    if (t < 8) g_goal[t] = g_vc[bi[0] * 8 + t];
}

__global__ void k_wprep(const float* __restrict__ fxW1, const float* __restrict__ fyW1,
                        const float* __restrict__ hyW1) {
    int t = blockIdx.x * blockDim.x + threadIdx.x;
    if (t < 4096) {
        g_A1[t] = fxW1[t] + fxW1[4096 + t];
        g_B1[t] = fxW1[8192 + t] - fxW1[t];
        g_A2[t] = fyW1[t] + fyW1[4096 + t];
        g_B2[t] = fyW1[8192 + t] - fyW1[t];
        if (t < 512) {
            g_Ay[t] = hyW1[t] + hyW1[512 + t];
            g_By[t] = hyW1[1024 + t] - hyW1[t];
        }
    }
}

// fused: x init MLP + node8 (P = vc@Ay, Q = vc@By), one node per block, 64 threads
__global__ void k_init(const float* __restrict__ W1, const float* __restrict__ b1,
                       const float* __restrict__ W2, const float* __restrict__ b2) {
    int i = blockIdx.x;
    int c = threadIdx.x;                 // 64 threads
    __shared__ float z[32], h[64];
    if (c < 8) {
        float vcv = g_vc[i * 8 + c];
        float gl  = g_goal[c];
        float d   = vcv - gl;
        z[c] = vcv; z[8 + c] = gl; z[16 + c] = d; z[24 + c] = d * d;
    }
    __syncthreads();
    float acc = b1[c];
    #pragma unroll
    for (int k = 0; k < 32; k++) acc += z[k] * W1[k * 64 + c];
    h[c] = fmaxf(acc, 0.0f);
    __syncthreads();
    float o = b2[c];
    #pragma unroll 16
    for (int k = 0; k < 64; k++) o += h[k] * W2[k * 64 + c];
    g_x[i * 64 + c] = o;
    // node8: P = vc@Ay, Q = vc@By (z[0..7] holds vc row)
    float r = 0.f, s = 0.f;
    #pragma unroll
    for (int k = 0; k < 8; k++) {
        r += z[k] * g_Ay[k * 64 + c];
        s += z[k] * g_By[k * 64 + c];
    }
    g_P[i * 64 + c] = r;
    g_Q[i * 64 + c] = s;
}

// ---------------- node GEMMs inside the loop ----------------
__global__ void k_node_A() {
    __shared__ float As[4096], Bs[4096], xs[64 * 33];
    int tid = threadIdx.x;
    int i0  = blockIdx.x * 32;
    for (int idx = tid; idx < 4096; idx += 256) { As[idx] = g_A1[idx]; Bs[idx] = g_B1[idx]; }
    for (int idx = tid; idx < 2048; idx += 256) {
        int nl = idx >> 6, k = idx & 63, i = i0 + nl;
        xs[k * 33 + nl] = (i < NN) ? g_x[i * 64 + k] : 0.f;
    }
    __syncthreads();
    int nl = tid >> 3, cg = tid & 7, c0 = cg * 8;
    float ap[8], aq[8];
    #pragma unroll
    for (int j = 0; j < 8; j++) { ap[j] = 0.f; aq[j] = 0.f; }
    #pragma unroll 8
    for (int k = 0; k < 64; k++) {
        float xv = xs[k * 33 + nl];
        float4 a0 = *(const float4*)&As[k * 64 + c0];
        float4 a1 = *(const float4*)&As[k * 64 + c0 + 4];
        float4 b0 = *(const float4*)&Bs[k * 64 + c0];
        float4 b1 = *(const float4*)&Bs[k * 64 + c0 + 4];
        FMA8(ap, xv, a0, a1);
        FMA8(aq, xv, b0, b1);
    }
    int i = i0 + nl;
    if (i < NN) {
        #pragma unroll
        for (int j = 0; j < 8; j++) {
            g_P[i * 64 + c0 + j]   = ap[j];
            g_Q[i * 64 + c0 + j]   = aq[j];
            g_agg[i * 64 + c0 + j] = NEG_INF;
        }
    }
}

__global__ void k_node_B() {
    __shared__ float As[4096], Bs[4096], xs[64 * 33];
    int tid = threadIdx.x;
    int i0  = blockIdx.x * 32;
    for (int idx = tid; idx < 4096; idx += 256) { As[idx] = g_A2[idx]; Bs[idx] = g_B2[idx]; }
    int nl = tid >> 3, cg = tid & 7, c0 = cg * 8;
    int i = i0 + nl;
    if (i < NN) {
        #pragma unroll
        for (int j = 0; j < 8; j++) {
            float a = g_agg[i * 64 + c0 + j];
            if (a == NEG_INF) a = 0.f;               // empty segment -> 0
            float xn = fmaxf(g_x[i * 64 + c0 + j], a);
            g_x[i * 64 + c0 + j] = xn;
            xs[(c0 + j) * 33 + nl] = xn;
        }
    } else {
        #pragma unroll
        for (int j = 0; j < 8; j++) xs[(c0 + j) * 33 + nl] = 0.f;
    }
    __syncthreads();
    float ap[8], aq[8];
    #pragma unroll
    for (int j = 0; j < 8; j++) { ap[j] = 0.f; aq[j] = 0.f; }
    #pragma unroll 8
    for (int k = 0; k < 64; k++) {
        float xv = xs[k * 33 + nl];
        float4 a0 = *(const float4*)&As[k * 64 + c0];
        float4 a1 = *(const float4*)&As[k * 64 + c0 + 4];
        float4 b0 = *(const float4*)&Bs[k * 64 + c0];
        float4 b1 = *(const float4*)&Bs[k * 64 + c0 + 4];
        FMA8(ap, xv, a0, a1);
        FMA8(aq, xv, b0, b1);
    }
    if (i < NN) {
        #pragma unroll
        for (int j = 0; j < 8; j++) {
            g_P[i * 64 + c0 + j] = ap[j];
            g_Q[i * 64 + c0 + j] = aq[j];
        }
    }
}

// ---------------- edge kernels ----------------
template <int MODE>
__global__ void k_edge_y(const float* __restrict__ b1, const float* __restrict__ W2,
                         const float* __restrict__ b2,
                         const int* __restrict__ src, const int* __restrict__ tgt) {
    __shared__ float Ws[4096];
    __shared__ float hs[64 * 33];
    int tid = threadIdx.x;
    int e0  = blockIdx.x * 32;
    for (int idx = tid; idx < 4096; idx += 256) Ws[idx] = W2[idx];
    int el = tid >> 3, cg = tid & 7, c0 = cg * 8;
    int e = e0 + el;
    int s = src[e], t = tgt[e];
    #pragma unroll
    for (int j = 0; j < 8; j++) {
        float h = g_P[t * 64 + c0 + j] + g_Q[s * 64 + c0 + j] + b1[c0 + j];
        hs[(c0 + j) * 33 + el] = fmaxf(h, 0.f);
    }
    __syncthreads();
    float acc[8];
    #pragma unroll
    for (int j = 0; j < 8; j++) acc[j] = b2[c0 + j];
    #pragma unroll 8
    for (int k = 0; k < 64; k++) {
        float hv = hs[k * 33 + el];
        float4 w0 = *(const float4*)&Ws[k * 64 + c0];
        float4 w1 = *(const float4*)&Ws[k * 64 + c0 + 4];
        FMA8(acc, hv, w0, w1);
    }
    if (MODE == 0) {
        #pragma unroll
        for (int j = 0; j < 8; j++) g_y[e * 64 + c0 + j] = acc[j];
    } else {
        #pragma unroll
        for (int j = 0; j < 8; j++) {
            float cur = g_y[e * 64 + c0 + j];
            g_y[e * 64 + c0 + j] = fmaxf(cur, acc[j]);
        }
    }
}

__global__ void k_fx_edge(const float* __restrict__ Wy, const float* __restrict__ b1,
                          const float* __restrict__ W2, const float* __restrict__ b2,
                          const int* __restrict__ src, const int* __restrict__ tgt) {
    __shared__ float Wys[4096];
    __shared__ float W2s[4096];
    __shared__ float ys[64 * 33];
    __shared__ float hs[64 * 33];
    int tid = threadIdx.x;
    int e0  = blockIdx.x * 32;
    for (int idx = tid; idx < 4096; idx += 256) { Wys[idx] = Wy[idx]; W2s[idx] = W2[idx]; }
    for (int idx = tid; idx < 2048; idx += 256) {
        int el = idx >> 6, k = idx & 63;
        ys[k * 33 + el] = g_y[(e0 + el) * 64 + k];
    }
    __syncthreads();
    int el = tid >> 3, cg = tid & 7, c0 = cg * 8;
    float acc[8];
    #pragma unroll
    for (int j = 0; j < 8; j++) acc[j] = 0.f;
    #pragma unroll 8
    for (int k = 0; k < 64; k++) {
        float yv = ys[k * 33 + el];
        float4 w0 = *(const float4*)&Wys[k * 64 + c0];
        float4 w1 = *(const float4*)&Wys[k * 64 + c0 + 4];
        FMA8(acc, yv, w0, w1);
    }
    int e = e0 + el;
    int s = src[e], t = tgt[e];
    #pragma unroll
    for (int j = 0; j < 8; j++) {
        float h = acc[j] + g_P[s * 64 + c0 + j] + g_Q[t * 64 + c0 + j] + b1[c0 + j];
        hs[(c0 + j) * 33 + el] = fmaxf(h, 0.f);
    }
    __syncthreads();
    #pragma unroll
    for (int j = 0; j < 8; j++) acc[j] = b2[c0 + j];
    #pragma unroll 8
    for (int k = 0; k < 64; k++) {
        float hv = hs[k * 33 + el];
        float4 w0 = *(const float4*)&W2s[k * 64 + c0];
        float4 w1 = *(const float4*)&W2s[k * 64 + c0 + 4];
        FMA8(acc, hv, w0, w1);
    }
    #pragma unroll
    for (int j = 0; j < 8; j++) atomicMaxFloat(&g_agg[t * 64 + c0 + j], acc[j]);
}

// ---------------- output machinery ----------------
__global__ void k_winner_init() {
    int i = blockIdx.x * blockDim.x + threadIdx.x;
    if (i < NN * NN) g_winner[i] = -1;
}

__global__ void k_winner(const int* __restrict__ src, const int* __restrict__ tgt) {
    int e = blockIdx.x * blockDim.x + threadIdx.x;
    if (e < NEDGE) atomicMax(&g_winner[src[e] * NN + tgt[e]], e);
}

// zero all NON-winner rows of out (576 MB streaming write; overlaps the loop)
__global__ void k_zero(float4* __restrict__ out4) {
    const int total = NN * NN * (EDIM / 4);   // 36M float4
    const float4 z = make_float4(0.f, 0.f, 0.f, 0.f);
    for (int idx = blockIdx.x * blockDim.x + threadIdx.x; idx < total;
         idx += gridDim.x * blockDim.x) {
        int row = idx >> 4;                   // 16 float4 per row
        if (g_winner[row] < 0) out4[idx] = z;
    }
}

// write the 24000 winner rows (6 MB)
__global__ void k_scatter(const int* __restrict__ src, const int* __restrict__ tgt,
                          float* __restrict__ out) {
    int idx = blockIdx.x * blockDim.x + threadIdx.x;
    if (idx < NEDGE * EDIM) {
        int e = idx >> 6, c = idx & 63;
        int s = src[e], t = tgt[e];
        long long slot = (long long)s * NN + t;
        if (g_winner[slot] == e) out[slot * 64 + c] = g_y[idx];
    }
}

__global__ void k_out_x(float* __restrict__ out) {
    int i = blockIdx.x * blockDim.x + threadIdx.x;
    if (i < NN * EDIM) out[(long long)NN * NN * EDIM + i] = g_x[i];
}

// ---------------- launch ----------------
extern "C" void kernel_launch(void* const* d_in, const int* in_sizes, int n_in,
                              void* d_out, int out_size) {
    const float* v      = (const float*)d_in[0];
    const float* labels = (const float*)d_in[1];
    const int*   ei     = (const int*)d_in[4];
    const float* hx_W1 = (const float*)d_in[6],  *hx_b1 = (const float*)d_in[7];
    const float* hx_W2 = (const float*)d_in[8],  *hx_b2 = (const float*)d_in[9];
    const float* hy_W1 = (const float*)d_in[10], *hy_b1 = (const float*)d_in[11];
    const float* hy_W2 = (const float*)d_in[12], *hy_b2 = (const float*)d_in[13];
    const float* fx_W1 = (const float*)d_in[14], *fx_b1 = (const float*)d_in[15];
    const float* fx_W2 = (const float*)d_in[16], *fx_b2 = (const float*)d_in[17];
    const float* fy_W1 = (const float*)d_in[18], *fy_b1 = (const float*)d_in[19];
    const float* fy_W2 = (const float*)d_in[20], *fy_b2 = (const float*)d_in[21];

    const int* src = ei;
    const int* tgt = ei + NEDGE;
    float* out = (float*)d_out;

    cudaStream_t s2;
    cudaStreamCreateWithFlags(&s2, cudaStreamNonBlocking);
    cudaEvent_t evFork, evJoin;
    cudaEventCreateWithFlags(&evFork, cudaEventDisableTiming);
    cudaEventCreateWithFlags(&evJoin, cudaEventDisableTiming);

    // ---- fork side stream at graph start: winner resolution + zero pass ----
    cudaEventRecord(evFork, 0);
    cudaStreamWaitEvent(s2, evFork, 0);
    k_winner_init<<<(NN * NN + 255) / 256, 256, 0, s2>>>();
    k_winner<<<(NEDGE + 255) / 256, 256, 0, s2>>>(src, tgt);
    k_zero<<<1184, 512, 0, s2>>>((float4*)out);
    cudaEventRecord(evJoin, s2);

    // ---- main stream: serial pipeline ----
    k_prep0<<<1, 256>>>(v, labels);
    k_wprep<<<16, 256>>>(fx_W1, fy_W1, hy_W1);
    k_init<<<NN, 64>>>(hx_W1, hx_b1, hx_W2, hx_b2);
    k_edge_y<0><<<NEDGE / 32, 256>>>(hy_b1, hy_W2, hy_b2, src, tgt);

    const int NODE_BLOCKS = (NN + 31) / 32;
    for (int it = 0; it < LOOPN; it++) {
        k_node_A<<<NODE_BLOCKS, 256>>>();
        k_fx_edge<<<NEDGE / 32, 256>>>(fx_W1 + 192 * 64, fx_b1, fx_W2, fx_b2, src, tgt);
        k_node_B<<<NODE_BLOCKS, 256>>>();
        k_edge_y<1><<<NEDGE / 32, 256>>>(fy_b1, fy_W2, fy_b2, src, tgt);
    }

    // ---- join, then final outputs ----
    cudaStreamWaitEvent(0, evJoin, 0);
    k_scatter<<<(NEDGE * EDIM + 255) / 256, 256>>>(src, tgt, out);
    k_out_x<<<(NN * EDIM + 255) / 256, 256>>>(out);
}

// round 9
// speedup vs baseline: 1.1024x; 1.0017x over previous
#include <cuda_runtime.h>
#include <cuda_bf16.h>

#define NN    1500
#define NEDGE 24000
#define EDIM  64
#define LOOPN 10
#define EBLK  750            // NEDGE/32 edge tiles
#define NTILE 47             // ceil(NN/32) node tiles

// ---------------- device scratch (static, allocation-free) ----------------
__device__ float g_vc[NN * 8];
__device__ float g_goal[8];
__device__ float g_x[NN * EDIM];
__device__ float g_y[NEDGE * EDIM];
__device__ float g_msg[NEDGE * EDIM];                  // fx messages (6 MB)
__device__ float g_Pf[NN * EDIM], g_Qf[NN * EDIM];     // fx-phase node projections
__device__ float g_Py[NN * EDIM], g_Qy[NN * EDIM];     // y-MLP node projections
__device__ float g_A1[EDIM * EDIM], g_B1[EDIM * EDIM];
__device__ float g_A2[EDIM * EDIM], g_B2[EDIM * EDIM];
__device__ float g_Ay[8 * EDIM],   g_By[8 * EDIM];
__device__ int   g_rowptr[NN + 1];
__device__ int   g_cols[NEDGE];
__device__ int   g_winner[NN * NN];   // 9 MB

#define NEG_INF __int_as_float(0xff800000)

#define FMA8(acc, v, w0, w1)                                   \
    {   acc[0] += (v) * (w0).x; acc[1] += (v) * (w0).y;        \
        acc[2] += (v) * (w0).z; acc[3] += (v) * (w0).w;        \
        acc[4] += (v) * (w1).x; acc[5] += (v) * (w1).y;        \
        acc[6] += (v) * (w1).z; acc[7] += (v) * (w1).w; }

// ---------------- prelude ----------------

// fused: vc build + goal argmax + combined-weight precompute (single block)
__global__ void k_prep(const float* __restrict__ v, const float* __restrict__ labels,
                       const float* __restrict__ fxW1, const float* __restrict__ fyW1,
                       const float* __restrict__ hyW1) {
    __shared__ float bv[256];
    __shared__ int   bi[256];
    int t = threadIdx.x;
    for (int i = t; i < NN; i += 256) {
        #pragma unroll
        for (int j = 0; j < 7; j++) g_vc[i * 8 + j] = v[i * 7 + j];
        g_vc[i * 8 + 7] = labels[i];
    }
    float best = -1e30f; int idx = 0;
    for (int i = t; i < NN; i += 256) {
        float l = labels[i];
        if (l > best) { best = l; idx = i; }
    }
    bv[t] = best; bi[t] = idx;
    __syncthreads();
    for (int s = 128; s > 0; s >>= 1) {
        if (t < s) {
            if (bv[t + s] > bv[t] || (bv[t + s] == bv[t] && bi[t + s] < bi[t])) {
                bv[t] = bv[t + s]; bi[t] = bi[t + s];
            }
        }
        __syncthreads();
    }
    if (t < 8) g_goal[t] = g_vc[bi[0] * 8 + t];
    // combined weights
    for (int i = t; i < 4096; i += 256) {
        g_A1[i] = fxW1[i] + fxW1[4096 + i];
        g_B1[i] = fxW1[8192 + i] - fxW1[i];
        g_A2[i] = fyW1[i] + fyW1[4096 + i];
        g_B2[i] = fyW1[8192 + i] - fyW1[i];
        if (i < 512) {
            g_Ay[i] = hyW1[i] + hyW1[512 + i];
            g_By[i] = hyW1[1024 + i] - hyW1[i];
        }
    }
}

// fused: x init MLP + hy node projections (Py = vc@Ay, Qy = vc@By)
__global__ void k_init(const float* __restrict__ W1, const float* __restrict__ b1,
                       const float* __restrict__ W2, const float* __restrict__ b2) {
    int i = blockIdx.x;
    int c = threadIdx.x;                 // 64 threads
    __shared__ float z[32], h[64];
    if (c < 8) {
        float vcv = g_vc[i * 8 + c];
        float gl  = g_goal[c];
        float d   = vcv - gl;
        z[c] = vcv; z[8 + c] = gl; z[16 + c] = d; z[24 + c] = d * d;
    }
    __syncthreads();
    float acc = b1[c];
    #pragma unroll
    for (int k = 0; k < 32; k++) acc += z[k] * W1[k * 64 + c];
    h[c] = fmaxf(acc, 0.0f);
    __syncthreads();
    float o = b2[c];
    #pragma unroll 16
    for (int k = 0; k < 64; k++) o += h[k] * W2[k * 64 + c];
    g_x[i * 64 + c] = o;
    float r = 0.f, s = 0.f;
    #pragma unroll
    for (int k = 0; k < 8; k++) {
        r += z[k] * g_Ay[k * 64 + c];
        s += z[k] * g_By[k * 64 + c];
    }
    g_Py[i * 64 + c] = r;
    g_Qy[i * 64 + c] = s;
}

// ---------------- fused edge-y + node_A kernel ----------------
// blocks [0, EBLK): y-MLP over edges using Py/Qy (MODE 0: y = out; 1: y = max(y,out))
// blocks [EBLK, EBLK+NTILE): node_A -> Pf = x@A1, Qf = x@B1
template <int MODE>
__global__ void k_eyA(const float* __restrict__ b1, const float* __restrict__ W2,
                      const float* __restrict__ b2,
                      const int* __restrict__ src, const int* __restrict__ tgt) {
    __shared__ float smA[4096];
    __shared__ float smB[4096];
    __shared__ float smX[64 * 33];
    int tid = threadIdx.x;
    int el = tid >> 3, cg = tid & 7, c0 = cg * 8;

    if (blockIdx.x < EBLK) {
        // ---- edge y-MLP ----
        float* Ws = smA;
        float* hs = smX;
        int e0 = blockIdx.x * 32;
        for (int idx = tid; idx < 4096; idx += 256) Ws[idx] = W2[idx];
        int e = e0 + el;
        int s = src[e], t = tgt[e];
        #pragma unroll
        for (int j = 0; j < 8; j++) {
            float h = g_Py[t * 64 + c0 + j] + g_Qy[s * 64 + c0 + j] + b1[c0 + j];
            hs[(c0 + j) * 33 + el] = fmaxf(h, 0.f);
        }
        __syncthreads();
        float acc[8];
        #pragma unroll
        for (int j = 0; j < 8; j++) acc[j] = b2[c0 + j];
        #pragma unroll 8
        for (int k = 0; k < 64; k++) {
            float hv = hs[k * 33 + el];
            float4 w0 = *(const float4*)&Ws[k * 64 + c0];
            float4 w1 = *(const float4*)&Ws[k * 64 + c0 + 4];
            FMA8(acc, hv, w0, w1);
        }
        if (MODE == 0) {
            #pragma unroll
            for (int j = 0; j < 8; j++) g_y[e * 64 + c0 + j] = acc[j];
        } else {
            #pragma unroll
            for (int j = 0; j < 8; j++) {
                float cur = g_y[e * 64 + c0 + j];
                g_y[e * 64 + c0 + j] = fmaxf(cur, acc[j]);
            }
        }
    } else {
        // ---- node_A: Pf = x@A1, Qf = x@B1 ----
        int i0 = (blockIdx.x - EBLK) * 32;
        for (int idx = tid; idx < 4096; idx += 256) { smA[idx] = g_A1[idx]; smB[idx] = g_B1[idx]; }
        for (int idx = tid; idx < 2048; idx += 256) {
            int nl2 = idx >> 6, k = idx & 63, i = i0 + nl2;
            smX[k * 33 + nl2] = (i < NN) ? g_x[i * 64 + k] : 0.f;
        }
        __syncthreads();
        float ap[8], aq[8];
        #pragma unroll
        for (int j = 0; j < 8; j++) { ap[j] = 0.f; aq[j] = 0.f; }
        #pragma unroll 8
        for (int k = 0; k < 64; k++) {
            float xv = smX[k * 33 + el];
            float4 a0 = *(const float4*)&smA[k * 64 + c0];
            float4 a1 = *(const float4*)&smA[k * 64 + c0 + 4];
            float4 b0 = *(const float4*)&smB[k * 64 + c0];
            float4 b1 = *(const float4*)&smB[k * 64 + c0 + 4];
            FMA8(ap, xv, a0, a1);
            FMA8(aq, xv, b0, b1);
        }
        int i = i0 + el;
        if (i < NN) {
            #pragma unroll
            for (int j = 0; j < 8; j++) {
                g_Pf[i * 64 + c0 + j] = ap[j];
                g_Qf[i * 64 + c0 + j] = aq[j];
            }
        }
    }
}

// ---------------- fx edge kernel (no atomics; writes msg) ----------------
__global__ void k_fx_edge(const float* __restrict__ Wy, const float* __restrict__ b1,
                          const float* __restrict__ W2, const float* __restrict__ b2,
                          const int* __restrict__ src, const int* __restrict__ tgt) {
    __shared__ float Wys[4096];
    __shared__ float W2s[4096];
    __shared__ float ys[64 * 33];
    __shared__ float hs[64 * 33];
    int tid = threadIdx.x;
    int e0  = blockIdx.x * 32;
    for (int idx = tid; idx < 4096; idx += 256) { Wys[idx] = Wy[idx]; W2s[idx] = W2[idx]; }
    for (int idx = tid; idx < 2048; idx += 256) {
        int el2 = idx >> 6, k = idx & 63;
        ys[k * 33 + el2] = g_y[(e0 + el2) * 64 + k];
    }
    __syncthreads();
    int el = tid >> 3, cg = tid & 7, c0 = cg * 8;
    float acc[8];
    #pragma unroll
    for (int j = 0; j < 8; j++) acc[j] = 0.f;
    #pragma unroll 8
    for (int k = 0; k < 64; k++) {
        float yv = ys[k * 33 + el];
        float4 w0 = *(const float4*)&Wys[k * 64 + c0];
        float4 w1 = *(const float4*)&Wys[k * 64 + c0 + 4];
        FMA8(acc, yv, w0, w1);
    }
    int e = e0 + el;
    int s = src[e], t = tgt[e];
    #pragma unroll
    for (int j = 0; j < 8; j++) {
        float h = acc[j] + g_Pf[s * 64 + c0 + j] + g_Qf[t * 64 + c0 + j] + b1[c0 + j];
        hs[(c0 + j) * 33 + el] = fmaxf(h, 0.f);
    }
    __syncthreads();
    #pragma unroll
    for (int j = 0; j < 8; j++) acc[j] = b2[c0 + j];
    #pragma unroll 8
    for (int k = 0; k < 64; k++) {
        float hv = hs[k * 33 + el];
        float4 w0 = *(const float4*)&W2s[k * 64 + c0];
        float4 w1 = *(const float4*)&W2s[k * 64 + c0 + 4];
        FMA8(acc, hv, w0, w1);
    }
    *(float4*)&g_msg[e * 64 + c0]     = make_float4(acc[0], acc[1], acc[2], acc[3]);
    *(float4*)&g_msg[e * 64 + c0 + 4] = make_float4(acc[4], acc[5], acc[6], acc[7]);
}

// ---------------- node_B: CSR gather-max + x update + A2/B2 GEMM ----------------
__global__ void k_node_B() {
    __shared__ float As[4096], Bs[4096], xs[64 * 33];
    int tid = threadIdx.x;
    int i0  = blockIdx.x * 32;
    for (int idx = tid; idx < 4096; idx += 256) { As[idx] = g_A2[idx]; Bs[idx] = g_B2[idx]; }
    int nl = tid >> 3, cg = tid & 7, c0 = cg * 8;
    int i = i0 + nl;
    if (i < NN) {
        float m[8];
        #pragma unroll
        for (int j = 0; j < 8; j++) m[j] = NEG_INF;
        int p0 = g_rowptr[i], p1 = g_rowptr[i + 1];
        for (int p = p0; p < p1; p++) {
            int e = g_cols[p];
            float4 a = *(const float4*)&g_msg[e * 64 + c0];
            float4 b = *(const float4*)&g_msg[e * 64 + c0 + 4];
            m[0] = fmaxf(m[0], a.x); m[1] = fmaxf(m[1], a.y);
            m[2] = fmaxf(m[2], a.z); m[3] = fmaxf(m[3], a.w);
            m[4] = fmaxf(m[4], b.x); m[5] = fmaxf(m[5], b.y);
            m[6] = fmaxf(m[6], b.z); m[7] = fmaxf(m[7], b.w);
        }
        if (p1 == p0) {
            #pragma unroll
            for (int j = 0; j < 8; j++) m[j] = 0.f;   // empty segment -> 0
        }
        #pragma unroll
        for (int j = 0; j < 8; j++) {
            float xn = fmaxf(g_x[i * 64 + c0 + j], m[j]);
            g_x[i * 64 + c0 + j] = xn;
            xs[(c0 + j) * 33 + nl] = xn;
        }
    } else {
        #pragma unroll
        for (int j = 0; j < 8; j++) xs[(c0 + j) * 33 + nl] = 0.f;
    }
    __syncthreads();
    float ap[8], aq[8];
    #pragma unroll
    for (int j = 0; j < 8; j++) { ap[j] = 0.f; aq[j] = 0.f; }
    #pragma unroll 8
    for (int k = 0; k < 64; k++) {
        float xv = xs[k * 33 + nl];
        float4 a0 = *(const float4*)&As[k * 64 + c0];
        float4 a1 = *(const float4*)&As[k * 64 + c0 + 4];
        float4 b0 = *(const float4*)&Bs[k * 64 + c0];
        float4 b1 = *(const float4*)&Bs[k * 64 + c0 + 4];
        FMA8(ap, xv, a0, a1);
        FMA8(aq, xv, b0, b1);
    }
    if (i < NN) {
        #pragma unroll
        for (int j = 0; j < 8; j++) {
            g_Py[i * 64 + c0 + j] = ap[j];
            g_Qy[i * 64 + c0 + j] = aq[j];
        }
    }
}

// ---------------- CSR build (single block, side stream) ----------------
__global__ void k_csr(const int* __restrict__ tgt) {
    __shared__ int cnt[1536];
    __shared__ int buf[1536];
    __shared__ int cur[1536];
    int tid = threadIdx.x;                 // 1024 threads
    for (int i = tid; i < 1536; i += 1024) cnt[i] = 0;
    __syncthreads();
    for (int e = tid; e < NEDGE; e += 1024) atomicAdd(&cnt[tgt[e]], 1);
    __syncthreads();
    // inclusive scan (ping-pong)
    int* s_ = cnt; int* d_ = buf;
    for (int off = 1; off < 1536; off <<= 1) {
        for (int i = tid; i < 1536; i += 1024)
            d_[i] = s_[i] + ((i >= off) ? s_[i - off] : 0);
        __syncthreads();
        int* tmp = s_; s_ = d_; d_ = tmp;
    }
    // s_ = inclusive scan
    if (tid == 0) g_rowptr[0] = 0;
    for (int i = tid; i < NN; i += 1024) g_rowptr[i + 1] = s_[i];
    for (int i = tid; i < 1536; i += 1024) cur[i] = (i == 0) ? 0 : s_[i - 1];
    __syncthreads();
    for (int e = tid; e < NEDGE; e += 1024) {
        int p = atomicAdd(&cur[tgt[e]], 1);
        g_cols[p] = e;
    }
}

// ---------------- output machinery ----------------
__global__ void k_winner_init() {
    int i = blockIdx.x * blockDim.x + threadIdx.x;
    if (i < NN * NN) g_winner[i] = -1;
}

__global__ void k_winner(const int* __restrict__ src, const int* __restrict__ tgt) {
    int e = blockIdx.x * blockDim.x + threadIdx.x;
    if (e < NEDGE) atomicMax(&g_winner[src[e] * NN + tgt[e]], e);
}

__global__ void k_zero(float4* __restrict__ out4) {
    const int total = NN * NN * (EDIM / 4);   // 36M float4
    const float4 z = make_float4(0.f, 0.f, 0.f, 0.f);
    for (int idx = blockIdx.x * blockDim.x + threadIdx.x; idx < total;
         idx += gridDim.x * blockDim.x) {
        int row = idx >> 4;
        if (g_winner[row] < 0) out4[idx] = z;
    }
}

__global__ void k_scatter(const int* __restrict__ src, const int* __restrict__ tgt,
                          float* __restrict__ out) {
    int idx = blockIdx.x * blockDim.x + threadIdx.x;
    if (idx < NEDGE * EDIM) {
        int e = idx >> 6, c = idx & 63;
        int s = src[e], t = tgt[e];
        long long slot = (long long)s * NN + t;
        if (g_winner[slot] == e) out[slot * 64 + c] = g_y[idx];
    }
}

__global__ void k_out_x(float* __restrict__ out) {
    int i = blockIdx.x * blockDim.x + threadIdx.x;
    if (i < NN * EDIM) out[(long long)NN * NN * EDIM + i] = g_x[i];
}

// ---------------- launch ----------------
extern "C" void kernel_launch(void* const* d_in, const int* in_sizes, int n_in,
                              void* d_out, int out_size) {
    const float* v      = (const float*)d_in[0];
    const float* labels = (const float*)d_in[1];
    const int*   ei     = (const int*)d_in[4];
    const float* hx_W1 = (const float*)d_in[6],  *hx_b1 = (const float*)d_in[7];
    const float* hx_W2 = (const float*)d_in[8],  *hx_b2 = (const float*)d_in[9];
    const float* hy_W1 = (const float*)d_in[10], *hy_b1 = (const float*)d_in[11];
    const float* hy_W2 = (const float*)d_in[12], *hy_b2 = (const float*)d_in[13];
    const float* fx_W1 = (const float*)d_in[14], *fx_b1 = (const float*)d_in[15];
    const float* fx_W2 = (const float*)d_in[16], *fx_b2 = (const float*)d_in[17];
    const float* fy_W1 = (const float*)d_in[18], *fy_b1 = (const float*)d_in[19];
    const float* fy_W2 = (const float*)d_in[20], *fy_b2 = (const float*)d_in[21];

    const int* src = ei;
    const int* tgt = ei + NEDGE;
    float* out = (float*)d_out;

    cudaStream_t s2;
    cudaStreamCreateWithFlags(&s2, cudaStreamNonBlocking);
    cudaEvent_t evFork, evCSR, evJoin;
    cudaEventCreateWithFlags(&evFork, cudaEventDisableTiming);
    cudaEventCreateWithFlags(&evCSR, cudaEventDisableTiming);
    cudaEventCreateWithFlags(&evJoin, cudaEventDisableTiming);

    cudaEventRecord(evFork, 0);

    // main pipeline head — submission order puts k_fx_edge at index 3 for ncu
    k_prep<<<1, 256>>>(v, labels, fx_W1, fy_W1, hy_W1);                      // #0
    k_init<<<NN, 64>>>(hx_W1, hx_b1, hx_W2, hx_b2);                          // #1
    k_eyA<0><<<EBLK + NTILE, 256>>>(hy_b1, hy_W2, hy_b2, src, tgt);          // #2
    k_fx_edge<<<EBLK, 256>>>(fx_W1 + 192 * 64, fx_b1, fx_W2, fx_b2, src, tgt); // #3 <- profiled

    // side stream: CSR + winner + zero (executes from capture start)
    cudaStreamWaitEvent(s2, evFork, 0);
    k_csr<<<1, 1024, 0, s2>>>(tgt);                                           // #4
    cudaEventRecord(evCSR, s2);
    k_winner_init<<<(NN * NN + 255) / 256, 256, 0, s2>>>();                   // #5
    k_winner<<<(NEDGE + 255) / 256, 256, 0, s2>>>(src, tgt);                  // #6
    k_zero<<<1184, 512, 0, s2>>>((float4*)out);                               // #7
    cudaEventRecord(evJoin, s2);

    // loop: fx_edge -> node_B -> ey+nodeA (3 kernels on the critical path)
    cudaStreamWaitEvent(0, evCSR, 0);
    for (int it = 0; it < LOOPN; it++) {
        if (it > 0)
            k_fx_edge<<<EBLK, 256>>>(fx_W1 + 192 * 64, fx_b1, fx_W2, fx_b2, src, tgt);
        k_node_B<<<NTILE, 256>>>();
        k_eyA<1><<<EBLK + NTILE, 256>>>(fy_b1, fy_W2, fy_b2, src, tgt);
    }

    // join side, then outputs
    cudaStreamWaitEvent(0, evJoin, 0);
    k_scatter<<<(NEDGE * EDIM + 255) / 256, 256>>>(src, tgt, out);
    k_out_x<<<(NN * EDIM + 255) / 256, 256>>>(out);
}

// round 10
// speedup vs baseline: 1.4977x; 1.3586x over previous
#include <cuda_runtime.h>
#include <cuda_bf16.h>

#define NN    1500
#define NEDGE 24000
#define EDIM  64
#define LOOPN 10
#define EB2   375            // NEDGE/64 edge tiles (64 edges per block)
#define NT2   24             // ceil(NN/64) node tiles (64 nodes per block)

// ---------------- device scratch (static, allocation-free) ----------------
__device__ float g_vc[NN * 8];
__device__ float g_goal[8];
__device__ float g_x[NN * EDIM];
__device__ float g_y[NEDGE * EDIM];
__device__ float g_msg[NEDGE * EDIM];
__device__ float g_Pf[NN * EDIM], g_Qf[NN * EDIM];
__device__ float g_Py[NN * EDIM], g_Qy[NN * EDIM];
__device__ float g_A1[EDIM * EDIM], g_B1[EDIM * EDIM];
__device__ float g_A2[EDIM * EDIM], g_B2[EDIM * EDIM];
__device__ float g_Ay[8 * EDIM],   g_By[8 * EDIM];
__device__ int   g_rowptr[NN + 1];
__device__ int   g_cols[NEDGE];
__device__ int   g_winner[NN * NN];

#define NEG_INF __int_as_float(0xff800000)

#define FMA8(acc, v, w0, w1)                                   \
    {   acc[0] += (v) * (w0).x; acc[1] += (v) * (w0).y;        \
        acc[2] += (v) * (w0).z; acc[3] += (v) * (w0).w;        \
        acc[4] += (v) * (w1).x; acc[5] += (v) * (w1).y;        \
        acc[6] += (v) * (w1).z; acc[7] += (v) * (w1).w; }

// dynamic smem sizes (floats)
#define FX_SM    (4096 + 4096 + 4160 + 4160)   // Wy, W2, ys, hs
#define EYA_SM   (4096 + 4096 + 4160)          // max(edge: W2+hs, node: A+B+xs)

// ---------------- prelude ----------------

__global__ void k_prep(const float* __restrict__ v, const float* __restrict__ labels,
                       const float* __restrict__ fxW1, const float* __restrict__ fyW1,
                       const float* __restrict__ hyW1) {
    __shared__ float bv[256];
    __shared__ int   bi[256];
    int t = threadIdx.x;
    for (int i = t; i < NN; i += 256) {
        #pragma unroll
        for (int j = 0; j < 7; j++) g_vc[i * 8 + j] = v[i * 7 + j];
        g_vc[i * 8 + 7] = labels[i];
    }
    float best = -1e30f; int idx = 0;
    for (int i = t; i < NN; i += 256) {
        float l = labels[i];
        if (l > best) { best = l; idx = i; }
    }
    bv[t] = best; bi[t] = idx;
    __syncthreads();
    for (int s = 128; s > 0; s >>= 1) {
        if (t < s) {
            if (bv[t + s] > bv[t] || (bv[t + s] == bv[t] && bi[t + s] < bi[t])) {
                bv[t] = bv[t + s]; bi[t] = bi[t + s];
            }
        }
        __syncthreads();
    }
    if (t < 8) g_goal[t] = g_vc[bi[0] * 8 + t];
    for (int i = t; i < 4096; i += 256) {
        g_A1[i] = fxW1[i] + fxW1[4096 + i];
        g_B1[i] = fxW1[8192 + i] - fxW1[i];
        g_A2[i] = fyW1[i] + fyW1[4096 + i];
        g_B2[i] = fyW1[8192 + i] - fyW1[i];
        if (i < 512) {
            g_Ay[i] = hyW1[i] + hyW1[512 + i];
            g_By[i] = hyW1[1024 + i] - hyW1[i];
        }
    }
}

__global__ void k_init(const float* __restrict__ W1, const float* __restrict__ b1,
                       const float* __restrict__ W2, const float* __restrict__ b2) {
    int i = blockIdx.x;
    int c = threadIdx.x;                 // 64 threads
    __shared__ float z[32], h[64];
    if (c < 8) {
        float vcv = g_vc[i * 8 + c];
        float gl  = g_goal[c];
        float d   = vcv - gl;
        z[c] = vcv; z[8 + c] = gl; z[16 + c] = d; z[24 + c] = d * d;
    }
    __syncthreads();
    float acc = b1[c];
    #pragma unroll
    for (int k = 0; k < 32; k++) acc += z[k] * W1[k * 64 + c];
    h[c] = fmaxf(acc, 0.0f);
    __syncthreads();
    float o = b2[c];
    #pragma unroll 16
    for (int k = 0; k < 64; k++) o += h[k] * W2[k * 64 + c];
    g_x[i * 64 + c] = o;
    float r = 0.f, s = 0.f;
    #pragma unroll
    for (int k = 0; k < 8; k++) {
        r += z[k] * g_Ay[k * 64 + c];
        s += z[k] * g_By[k * 64 + c];
    }
    g_Py[i * 64 + c] = r;
    g_Qy[i * 64 + c] = s;
}

// ---------------- fx edge kernel: 64 edges/block, 2 edges/thread ----------------
__global__ void __launch_bounds__(256)
k_fx_edge(const float* __restrict__ Wy, const float* __restrict__ b1,
          const float* __restrict__ W2, const float* __restrict__ b2,
          const int* __restrict__ src, const int* __restrict__ tgt) {
    extern __shared__ float sm[];
    float* Wys = sm;
    float* W2s = sm + 4096;
    float* ys  = sm + 8192;    // [64 k][65]
    float* hs  = sm + 12352;   // [64 col][65]
    int tid = threadIdx.x;
    int e0  = blockIdx.x * 64;
    for (int idx = tid; idx < 4096; idx += 256) { Wys[idx] = Wy[idx]; W2s[idx] = W2[idx]; }
    for (int idx = tid; idx < 4096; idx += 256) {
        int el2 = idx >> 6, k = idx & 63;
        ys[k * 65 + el2] = g_y[(e0 + el2) * 64 + k];
    }
    __syncthreads();
    int el = tid >> 3, cg = tid & 7, c0 = cg * 8;
    int eA = e0 + el, eB = e0 + el + 32;
    float accA[8], accB[8];
    #pragma unroll
    for (int j = 0; j < 8; j++) { accA[j] = 0.f; accB[j] = 0.f; }
    #pragma unroll 4
    for (int k = 0; k < 64; k++) {
        float yA = ys[k * 65 + el];
        float yB = ys[k * 65 + el + 32];
        float4 w0 = *(const float4*)&Wys[k * 64 + c0];
        float4 w1 = *(const float4*)&Wys[k * 64 + c0 + 4];
        FMA8(accA, yA, w0, w1);
        FMA8(accB, yB, w0, w1);
    }
    {
        int sA = src[eA], tA = tgt[eA];
        int sB = src[eB], tB = tgt[eB];
        float4 pA0 = *(const float4*)&g_Pf[sA * 64 + c0];
        float4 pA1 = *(const float4*)&g_Pf[sA * 64 + c0 + 4];
        float4 qA0 = *(const float4*)&g_Qf[tA * 64 + c0];
        float4 qA1 = *(const float4*)&g_Qf[tA * 64 + c0 + 4];
        float4 pB0 = *(const float4*)&g_Pf[sB * 64 + c0];
        float4 pB1 = *(const float4*)&g_Pf[sB * 64 + c0 + 4];
        float4 qB0 = *(const float4*)&g_Qf[tB * 64 + c0];
        float4 qB1 = *(const float4*)&g_Qf[tB * 64 + c0 + 4];
        hs[(c0 + 0) * 65 + el] = fmaxf(accA[0] + pA0.x + qA0.x + b1[c0 + 0], 0.f);
        hs[(c0 + 1) * 65 + el] = fmaxf(accA[1] + pA0.y + qA0.y + b1[c0 + 1], 0.f);
        hs[(c0 + 2) * 65 + el] = fmaxf(accA[2] + pA0.z + qA0.z + b1[c0 + 2], 0.f);
        hs[(c0 + 3) * 65 + el] = fmaxf(accA[3] + pA0.w + qA0.w + b1[c0 + 3], 0.f);
        hs[(c0 + 4) * 65 + el] = fmaxf(accA[4] + pA1.x + qA1.x + b1[c0 + 4], 0.f);
        hs[(c0 + 5) * 65 + el] = fmaxf(accA[5] + pA1.y + qA1.y + b1[c0 + 5], 0.f);
        hs[(c0 + 6) * 65 + el] = fmaxf(accA[6] + pA1.z + qA1.z + b1[c0 + 6], 0.f);
        hs[(c0 + 7) * 65 + el] = fmaxf(accA[7] + pA1.w + qA1.w + b1[c0 + 7], 0.f);
        hs[(c0 + 0) * 65 + el + 32] = fmaxf(accB[0] + pB0.x + qB0.x + b1[c0 + 0], 0.f);
        hs[(c0 + 1) * 65 + el + 32] = fmaxf(accB[1] + pB0.y + qB0.y + b1[c0 + 1], 0.f);
        hs[(c0 + 2) * 65 + el + 32] = fmaxf(accB[2] + pB0.z + qB0.z + b1[c0 + 2], 0.f);
        hs[(c0 + 3) * 65 + el + 32] = fmaxf(accB[3] + pB0.w + qB0.w + b1[c0 + 3], 0.f);
        hs[(c0 + 4) * 65 + el + 32] = fmaxf(accB[4] + pB1.x + qB1.x + b1[c0 + 4], 0.f);
        hs[(c0 + 5) * 65 + el + 32] = fmaxf(accB[5] + pB1.y + qB1.y + b1[c0 + 5], 0.f);
        hs[(c0 + 6) * 65 + el + 32] = fmaxf(accB[6] + pB1.z + qB1.z + b1[c0 + 6], 0.f);
        hs[(c0 + 7) * 65 + el + 32] = fmaxf(accB[7] + pB1.w + qB1.w + b1[c0 + 7], 0.f);
    }
    __syncthreads();
    #pragma unroll
    for (int j = 0; j < 8; j++) { accA[j] = b2[c0 + j]; accB[j] = b2[c0 + j]; }
    #pragma unroll 4
    for (int k = 0; k < 64; k++) {
        float hA = hs[k * 65 + el];
        float hB = hs[k * 65 + el + 32];
        float4 w0 = *(const float4*)&W2s[k * 64 + c0];
        float4 w1 = *(const float4*)&W2s[k * 64 + c0 + 4];
        FMA8(accA, hA, w0, w1);
        FMA8(accB, hB, w0, w1);
    }
    *(float4*)&g_msg[eA * 64 + c0]     = make_float4(accA[0], accA[1], accA[2], accA[3]);
    *(float4*)&g_msg[eA * 64 + c0 + 4] = make_float4(accA[4], accA[5], accA[6], accA[7]);
    *(float4*)&g_msg[eB * 64 + c0]     = make_float4(accB[0], accB[1], accB[2], accB[3]);
    *(float4*)&g_msg[eB * 64 + c0 + 4] = make_float4(accB[4], accB[5], accB[6], accB[7]);
}

// ---------------- fused edge-y + node_A: 2 outputs/thread ----------------
template <int MODE>
__global__ void __launch_bounds__(256)
k_eyA(const float* __restrict__ b1, const float* __restrict__ W2,
      const float* __restrict__ b2,
      const int* __restrict__ src, const int* __restrict__ tgt) {
    extern __shared__ float sm[];
    int tid = threadIdx.x;
    int el = tid >> 3, cg = tid & 7, c0 = cg * 8;

    if (blockIdx.x < EB2) {
        // ---- edge y-MLP (64 edges) ----
        float* Ws = sm;
        float* hs = sm + 4096;   // [64 col][65]
        int e0 = blockIdx.x * 64;
        for (int idx = tid; idx < 4096; idx += 256) Ws[idx] = W2[idx];
        int eA = e0 + el, eB = e0 + el + 32;
        {
            int sA = src[eA], tA = tgt[eA];
            int sB = src[eB], tB = tgt[eB];
            float4 pA0 = *(const float4*)&g_Py[tA * 64 + c0];
            float4 pA1 = *(const float4*)&g_Py[tA * 64 + c0 + 4];
            float4 qA0 = *(const float4*)&g_Qy[sA * 64 + c0];
            float4 qA1 = *(const float4*)&g_Qy[sA * 64 + c0 + 4];
            float4 pB0 = *(const float4*)&g_Py[tB * 64 + c0];
            float4 pB1 = *(const float4*)&g_Py[tB * 64 + c0 + 4];
            float4 qB0 = *(const float4*)&g_Qy[sB * 64 + c0];
            float4 qB1 = *(const float4*)&g_Qy[sB * 64 + c0 + 4];
            hs[(c0 + 0) * 65 + el] = fmaxf(pA0.x + qA0.x + b1[c0 + 0], 0.f);
            hs[(c0 + 1) * 65 + el] = fmaxf(pA0.y + qA0.y + b1[c0 + 1], 0.f);
            hs[(c0 + 2) * 65 + el] = fmaxf(pA0.z + qA0.z + b1[c0 + 2], 0.f);
            hs[(c0 + 3) * 65 + el] = fmaxf(pA0.w + qA0.w + b1[c0 + 3], 0.f);
            hs[(c0 + 4) * 65 + el] = fmaxf(pA1.x + qA1.x + b1[c0 + 4], 0.f);
            hs[(c0 + 5) * 65 + el] = fmaxf(pA1.y + qA1.y + b1[c0 + 5], 0.f);
            hs[(c0 + 6) * 65 + el] = fmaxf(pA1.z + qA1.z + b1[c0 + 6], 0.f);
            hs[(c0 + 7) * 65 + el] = fmaxf(pA1.w + qA1.w + b1[c0 + 7], 0.f);
            hs[(c0 + 0) * 65 + el + 32] = fmaxf(pB0.x + qB0.x + b1[c0 + 0], 0.f);
            hs[(c0 + 1) * 65 + el + 32] = fmaxf(pB0.y + qB0.y + b1[c0 + 1], 0.f);
            hs[(c0 + 2) * 65 + el + 32] = fmaxf(pB0.z + qB0.z + b1[c0 + 2], 0.f);
            hs[(c0 + 3) * 65 + el + 32] = fmaxf(pB0.w + qB0.w + b1[c0 + 3], 0.f);
            hs[(c0 + 4) * 65 + el + 32] = fmaxf(pB1.x + qB1.x + b1[c0 + 4], 0.f);
            hs[(c0 + 5) * 65 + el + 32] = fmaxf(pB1.y + qB1.y + b1[c0 + 5], 0.f);
            hs[(c0 + 6) * 65 + el + 32] = fmaxf(pB1.z + qB1.z + b1[c0 + 6], 0.f);
            hs[(c0 + 7) * 65 + el + 32] = fmaxf(pB1.w + qB1.w + b1[c0 + 7], 0.f);
        }
        __syncthreads();
        float accA[8], accB[8];
        #pragma unroll
        for (int j = 0; j < 8; j++) { accA[j] = b2[c0 + j]; accB[j] = b2[c0 + j]; }
        #pragma unroll 4
        for (int k = 0; k < 64; k++) {
            float hA = hs[k * 65 + el];
            float hB = hs[k * 65 + el + 32];
            float4 w0 = *(const float4*)&Ws[k * 64 + c0];
            float4 w1 = *(const float4*)&Ws[k * 64 + c0 + 4];
            FMA8(accA, hA, w0, w1);
            FMA8(accB, hB, w0, w1);
        }
        if (MODE == 0) {
            *(float4*)&g_y[eA * 64 + c0]     = make_float4(accA[0], accA[1], accA[2], accA[3]);
            *(float4*)&g_y[eA * 64 + c0 + 4] = make_float4(accA[4], accA[5], accA[6], accA[7]);
            *(float4*)&g_y[eB * 64 + c0]     = make_float4(accB[0], accB[1], accB[2], accB[3]);
            *(float4*)&g_y[eB * 64 + c0 + 4] = make_float4(accB[4], accB[5], accB[6], accB[7]);
        } else {
            float4 ya0 = *(const float4*)&g_y[eA * 64 + c0];
            float4 ya1 = *(const float4*)&g_y[eA * 64 + c0 + 4];
            float4 yb0 = *(const float4*)&g_y[eB * 64 + c0];
            float4 yb1 = *(const float4*)&g_y[eB * 64 + c0 + 4];
            *(float4*)&g_y[eA * 64 + c0] = make_float4(
                fmaxf(ya0.x, accA[0]), fmaxf(ya0.y, accA[1]),
                fmaxf(ya0.z, accA[2]), fmaxf(ya0.w, accA[3]));
            *(float4*)&g_y[eA * 64 + c0 + 4] = make_float4(
                fmaxf(ya1.x, accA[4]), fmaxf(ya1.y, accA[5]),
                fmaxf(ya1.z, accA[6]), fmaxf(ya1.w, accA[7]));
            *(float4*)&g_y[eB * 64 + c0] = make_float4(
                fmaxf(yb0.x, accB[0]), fmaxf(yb0.y, accB[1]),
                fmaxf(yb0.z, accB[2]), fmaxf(yb0.w, accB[3]));
            *(float4*)&g_y[eB * 64 + c0 + 4] = make_float4(
                fmaxf(yb1.x, accB[4]), fmaxf(yb1.y, accB[5]),
                fmaxf(yb1.z, accB[6]), fmaxf(yb1.w, accB[7]));
        }
    } else {
        // ---- node_A: Pf = x@A1, Qf = x@B1 (64 nodes) ----
        float* smA = sm;
        float* smB = sm + 4096;
        float* xs  = sm + 8192;   // [64 k][65]
        int i0 = (blockIdx.x - EB2) * 64;
        for (int idx = tid; idx < 4096; idx += 256) { smA[idx] = g_A1[idx]; smB[idx] = g_B1[idx]; }
        for (int idx = tid; idx < 4096; idx += 256) {
            int nl2 = idx >> 6, k = idx & 63, i = i0 + nl2;
            xs[k * 65 + nl2] = (i < NN) ? g_x[i * 64 + k] : 0.f;
        }
        __syncthreads();
        float apA[8], aqA[8], apB[8], aqB[8];
        #pragma unroll
        for (int j = 0; j < 8; j++) { apA[j] = 0.f; aqA[j] = 0.f; apB[j] = 0.f; aqB[j] = 0.f; }
        #pragma unroll 4
        for (int k = 0; k < 64; k++) {
            float xA = xs[k * 65 + el];
            float xB = xs[k * 65 + el + 32];
            float4 a0 = *(const float4*)&smA[k * 64 + c0];
            float4 a1 = *(const float4*)&smA[k * 64 + c0 + 4];
            float4 b0 = *(const float4*)&smB[k * 64 + c0];
            float4 b1 = *(const float4*)&smB[k * 64 + c0 + 4];
            FMA8(apA, xA, a0, a1);
            FMA8(aqA, xA, b0, b1);
            FMA8(apB, xB, a0, a1);
            FMA8(aqB, xB, b0, b1);
        }
        int iA = i0 + el, iB = i0 + el + 32;
        if (iA < NN) {
            *(float4*)&g_Pf[iA * 64 + c0]     = make_float4(apA[0], apA[1], apA[2], apA[3]);
            *(float4*)&g_Pf[iA * 64 + c0 + 4] = make_float4(apA[4], apA[5], apA[6], apA[7]);
            *(float4*)&g_Qf[iA * 64 + c0]     = make_float4(aqA[0], aqA[1], aqA[2], aqA[3]);
            *(float4*)&g_Qf[iA * 64 + c0 + 4] = make_float4(aqA[4], aqA[5], aqA[6], aqA[7]);
        }
        if (iB < NN) {
            *(float4*)&g_Pf[iB * 64 + c0]     = make_float4(apB[0], apB[1], apB[2], apB[3]);
            *(float4*)&g_Pf[iB * 64 + c0 + 4] = make_float4(apB[4], apB[5], apB[6], apB[7]);
            *(float4*)&g_Qf[iB * 64 + c0]     = make_float4(aqB[0], aqB[1], aqB[2], aqB[3]);
            *(float4*)&g_Qf[iB * 64 + c0 + 4] = make_float4(aqB[4], aqB[5], aqB[6], aqB[7]);
        }
    }
}

// ---------------- node_B: CSR gather-max + x update + A2/B2 GEMM ----------------
__global__ void __launch_bounds__(256)
k_node_B() {
    extern __shared__ float sm[];
    float* smA = sm;
    float* smB = sm + 4096;
    float* xs  = sm + 8192;   // [64 k][65]
    int tid = threadIdx.x;
    int i0  = blockIdx.x * 64;
    for (int idx = tid; idx < 4096; idx += 256) { smA[idx] = g_A2[idx]; smB[idx] = g_B2[idx]; }
    int el = tid >> 3, cg = tid & 7, c0 = cg * 8;

    #pragma unroll
    for (int half = 0; half < 2; half++) {
        int nl = el + half * 32;
        int i = i0 + nl;
        if (i < NN) {
            float m[8];
            #pragma unroll
            for (int j = 0; j < 8; j++) m[j] = NEG_INF;
            int p0 = g_rowptr[i], p1 = g_rowptr[i + 1];
            for (int p = p0; p < p1; p++) {
                int e = g_cols[p];
                float4 a = *(const float4*)&g_msg[e * 64 + c0];
                float4 b = *(const float4*)&g_msg[e * 64 + c0 + 4];
                m[0] = fmaxf(m[0], a.x); m[1] = fmaxf(m[1], a.y);
                m[2] = fmaxf(m[2], a.z); m[3] = fmaxf(m[3], a.w);
                m[4] = fmaxf(m[4], b.x); m[5] = fmaxf(m[5], b.y);
                m[6] = fmaxf(m[6], b.z); m[7] = fmaxf(m[7], b.w);
            }
            if (p1 == p0) {
                #pragma unroll
                for (int j = 0; j < 8; j++) m[j] = 0.f;
            }
            #pragma unroll
            for (int j = 0; j < 8; j++) {
                float xn = fmaxf(g_x[i * 64 + c0 + j], m[j]);
                g_x[i * 64 + c0 + j] = xn;
                xs[(c0 + j) * 65 + nl] = xn;
            }
        } else {
            #pragma unroll
            for (int j = 0; j < 8; j++) xs[(c0 + j) * 65 + nl] = 0.f;
        }
    }
    __syncthreads();
    float apA[8], aqA[8], apB[8], aqB[8];
    #pragma unroll
    for (int j = 0; j < 8; j++) { apA[j] = 0.f; aqA[j] = 0.f; apB[j] = 0.f; aqB[j] = 0.f; }
    #pragma unroll 4
    for (int k = 0; k < 64; k++) {
        float xA = xs[k * 65 + el];
        float xB = xs[k * 65 + el + 32];
        float4 a0 = *(const float4*)&smA[k * 64 + c0];
        float4 a1 = *(const float4*)&smA[k * 64 + c0 + 4];
        float4 b0 = *(const float4*)&smB[k * 64 + c0];
        float4 b1 = *(const float4*)&smB[k * 64 + c0 + 4];
        FMA8(apA, xA, a0, a1);
        FMA8(aqA, xA, b0, b1);
        FMA8(apB, xB, a0, a1);
        FMA8(aqB, xB, b0, b1);
    }
    int iA = i0 + el, iB = i0 + el + 32;
    if (iA < NN) {
        *(float4*)&g_Py[iA * 64 + c0]     = make_float4(apA[0], apA[1], apA[2], apA[3]);
        *(float4*)&g_Py[iA * 64 + c0 + 4] = make_float4(apA[4], apA[5], apA[6], apA[7]);
        *(float4*)&g_Qy[iA * 64 + c0]     = make_float4(aqA[0], aqA[1], aqA[2], aqA[3]);
        *(float4*)&g_Qy[iA * 64 + c0 + 4] = make_float4(aqA[4], aqA[5], aqA[6], aqA[7]);
    }
    if (iB < NN) {
        *(float4*)&g_Py[iB * 64 + c0]     = make_float4(apB[0], apB[1], apB[2], apB[3]);
        *(float4*)&g_Py[iB * 64 + c0 + 4] = make_float4(apB[4], apB[5], apB[6], apB[7]);
        *(float4*)&g_Qy[iB * 64 + c0]     = make_float4(aqB[0], aqB[1], aqB[2], aqB[3]);
        *(float4*)&g_Qy[iB * 64 + c0 + 4] = make_float4(aqB[4], aqB[5], aqB[6], aqB[7]);
    }
}

// ---------------- CSR build (single block, side stream) ----------------
__global__ void k_csr(const int* __restrict__ tgt) {
    __shared__ int cnt[1536];
    __shared__ int buf[1536];
    __shared__ int cur[1536];
    int tid = threadIdx.x;                 // 1024 threads
    for (int i = tid; i < 1536; i += 1024) cnt[i] = 0;
    __syncthreads();
    for (int e = tid; e < NEDGE; e += 1024) atomicAdd(&cnt[tgt[e]], 1);
    __syncthreads();
    int* s_ = cnt; int* d_ = buf;
    for (int off = 1; off < 1536; off <<= 1) {
        for (int i = tid; i < 1536; i += 1024)
            d_[i] = s_[i] + ((i >= off) ? s_[i - off] : 0);
        __syncthreads();
        int* tmp = s_; s_ = d_; d_ = tmp;
    }
    if (tid == 0) g_rowptr[0] = 0;
    for (int i = tid; i < NN; i += 1024) g_rowptr[i + 1] = s_[i];
    for (int i = tid; i < 1536; i += 1024) cur[i] = (i == 0) ? 0 : s_[i - 1];
    __syncthreads();
    for (int e = tid; e < NEDGE; e += 1024) {
        int p = atomicAdd(&cur[tgt[e]], 1);
        g_cols[p] = e;
    }
}

// ---------------- output machinery ----------------
__global__ void k_winner_init() {
    int i = blockIdx.x * blockDim.x + threadIdx.x;
    if (i < NN * NN) g_winner[i] = -1;
}

__global__ void k_winner(const int* __restrict__ src, const int* __restrict__ tgt) {
    int e = blockIdx.x * blockDim.x + threadIdx.x;
    if (e < NEDGE) atomicMax(&g_winner[src[e] * NN + tgt[e]], e);
}

__global__ void k_zero(float4* __restrict__ out4) {
    const int total = NN * NN * (EDIM / 4);
    const float4 z = make_float4(0.f, 0.f, 0.f, 0.f);
    for (int idx = blockIdx.x * blockDim.x + threadIdx.x; idx < total;
         idx += gridDim.x * blockDim.x) {
        int row = idx >> 4;
        if (g_winner[row] < 0) out4[idx] = z;
    }
}

__global__ void k_scatter(const int* __restrict__ src, const int* __restrict__ tgt,
                          float* __restrict__ out) {
    int idx = blockIdx.x * blockDim.x + threadIdx.x;
    if (idx < NEDGE * EDIM) {
        int e = idx >> 6, c = idx & 63;
        int s = src[e], t = tgt[e];
        long long slot = (long long)s * NN + t;
        if (g_winner[slot] == e) out[slot * 64 + c] = g_y[idx];
    }
}

__global__ void k_out_x(float* __restrict__ out) {
    int i = blockIdx.x * blockDim.x + threadIdx.x;
    if (i < NN * EDIM) out[(long long)NN * NN * EDIM + i] = g_x[i];
}

// ---------------- launch ----------------
extern "C" void kernel_launch(void* const* d_in, const int* in_sizes, int n_in,
                              void* d_out, int out_size) {
    const float* v      = (const float*)d_in[0];
    const float* labels = (const float*)d_in[1];
    const int*   ei     = (const int*)d_in[4];
    const float* hx_W1 = (const float*)d_in[6],  *hx_b1 = (const float*)d_in[7];
    const float* hx_W2 = (const float*)d_in[8],  *hx_b2 = (const float*)d_in[9];
    const float* hy_W1 = (const float*)d_in[10], *hy_b1 = (const float*)d_in[11];
    const float* hy_W2 = (const float*)d_in[12], *hy_b2 = (const float*)d_in[13];
    const float* fx_W1 = (const float*)d_in[14], *fx_b1 = (const float*)d_in[15];
    const float* fx_W2 = (const float*)d_in[16], *fx_b2 = (const float*)d_in[17];
    const float* fy_W1 = (const float*)d_in[18], *fy_b1 = (const float*)d_in[19];
    const float* fy_W2 = (const float*)d_in[20], *fy_b2 = (const float*)d_in[21];

    const int* src = ei;
    const int* tgt = ei + NEDGE;
    float* out = (float*)d_out;

    static bool attr_done = false;
    if (!attr_done) {
        cudaFuncSetAttribute(k_fx_edge, cudaFuncAttributeMaxDynamicSharedMemorySize,
                             FX_SM * sizeof(float));
        cudaFuncSetAttribute(k_eyA<0>, cudaFuncAttributeMaxDynamicSharedMemorySize,
                             EYA_SM * sizeof(float));
        cudaFuncSetAttribute(k_eyA<1>, cudaFuncAttributeMaxDynamicSharedMemorySize,
                             EYA_SM * sizeof(float));
        cudaFuncSetAttribute(k_node_B, cudaFuncAttributeMaxDynamicSharedMemorySize,
                             EYA_SM * sizeof(float));
        attr_done = true;
    }

    cudaStream_t s2;
    cudaStreamCreateWithFlags(&s2, cudaStreamNonBlocking);
    cudaEvent_t evFork, evCSR, evJoin;
    cudaEventCreateWithFlags(&evFork, cudaEventDisableTiming);
    cudaEventCreateWithFlags(&evCSR, cudaEventDisableTiming);
    cudaEventCreateWithFlags(&evJoin, cudaEventDisableTiming);

    cudaEventRecord(evFork, 0);

    // main pipeline head — k_fx_edge stays at submission index 3 for ncu
    k_prep<<<1, 256>>>(v, labels, fx_W1, fy_W1, hy_W1);                       // #0
    k_init<<<NN, 64>>>(hx_W1, hx_b1, hx_W2, hx_b2);                           // #1
    k_eyA<0><<<EB2 + NT2, 256, EYA_SM * sizeof(float)>>>(hy_b1, hy_W2, hy_b2, src, tgt); // #2
    k_fx_edge<<<EB2, 256, FX_SM * sizeof(float)>>>(fx_W1 + 192 * 64, fx_b1, fx_W2, fx_b2, src, tgt); // #3

    // side stream: CSR + winner + zero
    cudaStreamWaitEvent(s2, evFork, 0);
    k_csr<<<1, 1024, 0, s2>>>(tgt);
    cudaEventRecord(evCSR, s2);
    k_winner_init<<<(NN * NN + 255) / 256, 256, 0, s2>>>();
    k_winner<<<(NEDGE + 255) / 256, 256, 0, s2>>>(src, tgt);
    k_zero<<<1184, 512, 0, s2>>>((float4*)out);
    cudaEventRecord(evJoin, s2);

    // loop: fx_edge -> node_B -> ey+nodeA
    cudaStreamWaitEvent(0, evCSR, 0);
    for (int it = 0; it < LOOPN; it++) {
        if (it > 0)
            k_fx_edge<<<EB2, 256, FX_SM * sizeof(float)>>>(fx_W1 + 192 * 64, fx_b1, fx_W2, fx_b2, src, tgt);
        k_node_B<<<NT2, 256, EYA_SM * sizeof(float)>>>();
        k_eyA<1><<<EB2 + NT2, 256, EYA_SM * sizeof(float)>>>(fy_b1, fy_W2, fy_b2, src, tgt);
    }

    // join side, then outputs
    cudaStreamWaitEvent(0, evJoin, 0);
    k_scatter<<<(NEDGE * EDIM + 255) / 256, 256>>>(src, tgt, out);
    k_out_x<<<(NN * EDIM + 255) / 256, 256>>>(out);
}